// round 15
// baseline (speedup 1.0000x reference)
#include <cuda_runtime.h>
#include <cuda_bf16.h>
#include <math.h>
#include <stdint.h>

// ---------------- problem constants ----------------
#define BATCH  2
#define LSEQ   8192
#define DMODEL 1024
#define NPROJ  6176
#define CONVD  5120
#define DINNER 1024
#define NH     32
#define DST    64
#define HDIM   32
#define CHK    128
#define NCH    64
#define MROWS  (BATCH*LSEQ)   // 16384

// split-bf16 GEMM constants
#define K2     2048            // stored: [hi | lo]
#define BM     128
#define BN     128
#define BK     64
#define NSTAGE 3
#define NCHUNK 48              // logical K = 3072

// ---------------- scratch (device globals) --------
__device__ float g_xbcza[(size_t)MROWS * NPROJ];
__device__ float g_conv [(size_t)MROWS * CONVD];
__device__ float g_acum [(size_t)MROWS * NH];
__device__ float g_y    [(size_t)MROWS * DINNER];
__device__ float g_states[(size_t)BATCH*NCH*NH*HDIM*DST];
__device__ float g_prevs [(size_t)BATCH*NCH*NH*HDIM*DST];
__device__ float g_dc   [BATCH*NCH*NH];

__device__ __nv_bfloat16 g_uS   [(size_t)MROWS * K2];
__device__ __nv_bfloat16 g_WinS [(size_t)NPROJ * K2 + 1024];
__device__ __nv_bfloat16 g_yS   [(size_t)MROWS * K2];
__device__ __nv_bfloat16 g_WoutS[(size_t)1024 * K2];

// ---------------- helpers ----------------
__device__ __forceinline__ uint32_t smem_u32(const void* p) {
    uint32_t a;
    asm("{ .reg .u64 t; cvta.to.shared.u64 t, %1; cvt.u32.u64 %0, t; }"
        : "=r"(a) : "l"(p));
    return a;
}
#define SW128(o) ((o) ^ (((o) >> 3) & 0x70))

__device__ __forceinline__ void ldsm4(uint32_t* r, uint32_t addr) {
    asm volatile("ldmatrix.sync.aligned.m8n8.x4.shared.b16 {%0,%1,%2,%3}, [%4];"
        : "=r"(r[0]), "=r"(r[1]), "=r"(r[2]), "=r"(r[3]) : "r"(addr));
}
__device__ __forceinline__ void mma16816(float* c, const uint32_t* a,
                                         uint32_t b0, uint32_t b1) {
    asm volatile(
        "mma.sync.aligned.m16n8k16.row.col.f32.bf16.bf16.f32 "
        "{%0,%1,%2,%3}, {%4,%5,%6,%7}, {%8,%9}, {%0,%1,%2,%3};"
        : "+f"(c[0]), "+f"(c[1]), "+f"(c[2]), "+f"(c[3])
        : "r"(a[0]), "r"(a[1]), "r"(a[2]), "r"(a[3]), "r"(b0), "r"(b1));
}
__device__ __forceinline__ uint32_t pack2(__nv_bfloat16 a, __nv_bfloat16 b) {
    return (uint32_t)__bfloat16_as_ushort(a) | ((uint32_t)__bfloat16_as_ushort(b) << 16);
}

// ============================================================
// split kernel: fp32 [M,1024] -> bf16 [M,2048] as [hi|lo]
// ============================================================
__global__ __launch_bounds__(256)
void split2(const float* __restrict__ X, __nv_bfloat16* __restrict__ Y)
{
    size_t idx = (size_t)blockIdx.x * 256 + threadIdx.x;
    size_t m = idx >> 9;
    int k2 = (int)(idx & 511) * 2;
    float2 x = *(const float2*)&X[m * 1024 + k2];
    __nv_bfloat16 h0 = __float2bfloat16(x.x);
    __nv_bfloat16 h1 = __float2bfloat16(x.y);
    __nv_bfloat16 l0 = __float2bfloat16(x.x - __bfloat162float(h0));
    __nv_bfloat16 l1 = __float2bfloat16(x.y - __bfloat162float(h1));
    __nv_bfloat162 hi; hi.x = h0; hi.y = h1;
    __nv_bfloat162 lo; lo.x = l0; lo.y = l1;
    __nv_bfloat16* row = Y + m * (size_t)K2;
    *(__nv_bfloat162*)&row[k2]        = hi;
    *(__nv_bfloat162*)&row[1024 + k2] = lo;
}

// ============================================================
// bf16 warp-MMA GEMM, m_base offset
// ============================================================
__global__ __launch_bounds__(256, 2)
void gemm_mma(float* __restrict__ C,
              const __nv_bfloat16* __restrict__ A,
              const __nv_bfloat16* __restrict__ B,
              int N_out, int ldc, int m_base)
{
    extern __shared__ char smem[];
    const int tid  = threadIdx.x;
    const int wid  = tid >> 5;
    const int lane = tid & 31;
    const int m0 = m_base + blockIdx.y * BM;
    const int n0 = blockIdx.x * BN;
    const int wm = (wid >> 2) * 64;
    const int wn = (wid & 3) * 32;

    char* tiles = smem;

    auto fill = [&](int chunk) {
        int s = chunk % NSTAGE;
        int part = chunk >> 4;
        int ko = (chunk & 15) * BK;
        int aoff = (part == 1) ? 1024 : 0;
        int boff = (part == 2) ? 1024 : 0;
        char* As = tiles + s * 32768;
        char* Bs = As + 16384;
        const char* Ag = (const char*)(A + (size_t)m0 * K2 + aoff + ko);
        const char* Bg = (const char*)(B + (size_t)n0 * K2 + boff + ko);
        uint32_t Asb = smem_u32(As), Bsb = smem_u32(Bs);
#pragma unroll
        for (int r = 0; r < 4; r++) {
            int cid = tid + r * 256;
            int row = cid >> 3, col = cid & 7;
            uint32_t dst = Asb + SW128(row * 128 + col * 16);
            const void* src = Ag + (size_t)row * (K2 * 2) + col * 16;
            asm volatile("cp.async.cg.shared.global [%0], [%1], 16;" :: "r"(dst), "l"(src));
        }
#pragma unroll
        for (int r = 0; r < 4; r++) {
            int cid = tid + r * 256;
            int row = cid >> 3, col = cid & 7;
            uint32_t dst = Bsb + SW128(row * 128 + col * 16);
            const void* src = Bg + (size_t)row * (K2 * 2) + col * 16;
            asm volatile("cp.async.cg.shared.global [%0], [%1], 16;" :: "r"(dst), "l"(src));
        }
        asm volatile("cp.async.commit_group;" ::: "memory");
    };

    float acc[4][4][4];
#pragma unroll
    for (int mi = 0; mi < 4; mi++)
#pragma unroll
        for (int ni = 0; ni < 4; ni++)
#pragma unroll
            for (int r = 0; r < 4; r++) acc[mi][ni][r] = 0.f;

    fill(0); fill(1);

    const int lrow = lane & 15;
    const int lcol = lane >> 4;

    for (int i = 0; i < NCHUNK; i++) {
        int s = i % NSTAGE;
        if (i + 1 < NCHUNK)
            asm volatile("cp.async.wait_group 1;" ::: "memory");
        else
            asm volatile("cp.async.wait_group 0;" ::: "memory");
        __syncthreads();

        if (i + 2 < NCHUNK) fill(i + 2);

        uint32_t Asb = smem_u32(tiles + s * 32768);
        uint32_t Bsb = Asb + 16384;

#pragma unroll
        for (int ks = 0; ks < 4; ks++) {
            uint32_t a[4][4], b[2][4];
#pragma unroll
            for (int mi = 0; mi < 4; mi++)
                ldsm4(a[mi], Asb + SW128((wm + mi * 16 + lrow) * 128 + (ks * 2 + lcol) * 16));
#pragma unroll
            for (int bi = 0; bi < 2; bi++)
                ldsm4(b[bi], Bsb + SW128((wn + bi * 16 + lrow) * 128 + (ks * 2 + lcol) * 16));
#pragma unroll
            for (int mi = 0; mi < 4; mi++)
#pragma unroll
                for (int ni = 0; ni < 4; ni++) {
                    int bi = ni >> 1, hf = ni & 1;
                    mma16816(acc[mi][ni], a[mi], b[bi][hf], b[bi][2 + hf]);
                }
        }
    }

    const int gr = lane >> 2;
    const int gc = (lane & 3) * 2;
#pragma unroll
    for (int mi = 0; mi < 4; mi++) {
        int m = m0 + wm + mi * 16 + gr;
#pragma unroll
        for (int ni = 0; ni < 4; ni++) {
            int n = n0 + wn + ni * 8 + gc;
            if (n < N_out) {
                float2 v0 = make_float2(acc[mi][ni][0], acc[mi][ni][1]);
                float2 v1 = make_float2(acc[mi][ni][2], acc[mi][ni][3]);
                *(float2*)&C[(size_t)m * ldc + n]       = v0;
                *(float2*)&C[(size_t)(m + 8) * ldc + n] = v1;
            }
        }
    }
}

// ============================================================
// depthwise causal conv (register-blocked 4ch x 4t), m_base offset
// ============================================================
__global__ __launch_bounds__(256)
void conv_kernel(const float* __restrict__ cw, const float* __restrict__ cb, int m_base)
{
    int c4 = blockIdx.x * 256 + threadIdx.x;
    int ch = c4 * 4;
    int m0 = m_base + blockIdx.y * 4;
    int t0 = m0 & (LSEQ - 1);

    const float4* wp = (const float4*)(cw + ch * 4);
    float4 w0 = wp[0], w1 = wp[1], w2 = wp[2], w3 = wp[3];
    float4 bias = *(const float4*)(cb + ch);

    float4 r[7];
    const float* base = g_xbcza + (size_t)m0 * NPROJ + ch;
#pragma unroll
    for (int k = 0; k < 7; k++) {
        int tt = t0 - 3 + k;
        if (tt >= 0)
            r[k] = *(const float4*)(base + (long)(k - 3) * NPROJ);
        else
            r[k] = make_float4(0.f, 0.f, 0.f, 0.f);
    }

    float* outbase = g_conv + (size_t)m0 * CONVD + ch;
#pragma unroll
    for (int j = 0; j < 4; j++) {
        float4 o = bias;
        o.x += w0.x * r[j].x + w0.y * r[j+1].x + w0.z * r[j+2].x + w0.w * r[j+3].x;
        o.y += w1.x * r[j].y + w1.y * r[j+1].y + w1.z * r[j+2].y + w1.w * r[j+3].y;
        o.z += w2.x * r[j].z + w2.y * r[j+1].z + w2.z * r[j+2].z + w2.w * r[j+3].z;
        o.w += w3.x * r[j].w + w3.y * r[j+1].w + w3.z * r[j+2].w + w3.w * r[j+3].w;
        *(float4*)(outbase + (size_t)j * CONVD) = o;
    }
}

// ============================================================
// per-(chunk,head) SSD chunk kernel — tensor-core, 81KB smem (2 CTA/SM)
// ============================================================
#define CB_C_HI   0u
#define CB_C_LO   16384u
#define CB_B_HI   32768u
#define CB_B_LO   49152u
#define CB_M_HI   0u
#define CB_M_LO   32768u
#define CB_XT_HI  65536u
#define CB_XT_LO  73728u
#define CB_BTD_HI 0u
#define CB_BTD_LO 16384u
#define CB_SA     81920u
#define CB_SDS    82432u
#define CB_SMEM   82944u

__global__ __launch_bounds__(256, 2)
void chunk_kernel(int b, int c0)
{
    extern __shared__ char smem[];
    float* sA  = (float*)(smem + CB_SA);
    float* sDs = (float*)(smem + CB_SDS);
    const uint32_t sb0 = smem_u32(smem);

    const int tid = threadIdx.x;
    const int wid = tid >> 5, lane = tid & 31;
    const int bid = blockIdx.x;
    const int h = bid & 31;
    const int c = c0 + (bid >> 5);
    const size_t m0 = (size_t)b * LSEQ + (size_t)c * CHK;

    // ---- dt = softplus(A_log); inclusive scan of -dt ----
    if (tid < CHK) {
        float alog = g_xbcza[(m0 + tid) * NPROJ + (CONVD + DINNER) + h];
        float dt = alog > 20.f ? alog : log1pf(expf(alog));
        sA[tid] = dt;
    }
    __syncthreads();
    for (int off = 1; off < CHK; off <<= 1) {
        float v = 0.f;
        if (tid < CHK && tid >= off) v = sA[tid - off];
        __syncthreads();
        if (tid < CHK) sA[tid] += v;
        __syncthreads();
    }
    if (tid < CHK) sA[tid] = -sA[tid];
    __syncthreads();
    float aLast = sA[CHK - 1];
    if (tid < CHK) {
        sDs[tid] = __expf(aLast - sA[tid]);
        g_acum[(m0 + tid) * NH + h] = sA[tid];
    }
    if (tid == 0) g_dc[(b * NCH + c) * NH + h] = __expf(aLast);
    __syncthreads();

    // ---- convert C,B -> bf16 hi/lo tiles ----
    for (int u = tid; u < 128 * 16; u += 256) {
        int l = u >> 4, nq = (u & 15) * 4;
        const float* crow = &g_conv[(m0 + l) * CONVD];
        float4 vc = *(const float4*)&crow[DINNER + NH * DST + h * DST + nq];
        float4 vb = *(const float4*)&crow[DINNER + h * DST + nq];
        uint32_t off = SW128((uint32_t)(l * 128 + nq * 2));
        {
            __nv_bfloat16 h0 = __float2bfloat16(vc.x), h1 = __float2bfloat16(vc.y);
            __nv_bfloat16 h2 = __float2bfloat16(vc.z), h3 = __float2bfloat16(vc.w);
            *(uint2*)(smem + CB_C_HI + off) = make_uint2(pack2(h0, h1), pack2(h2, h3));
            __nv_bfloat16 q0 = __float2bfloat16(vc.x - __bfloat162float(h0));
            __nv_bfloat16 q1 = __float2bfloat16(vc.y - __bfloat162float(h1));
            __nv_bfloat16 q2 = __float2bfloat16(vc.z - __bfloat162float(h2));
            __nv_bfloat16 q3 = __float2bfloat16(vc.w - __bfloat162float(h3));
            *(uint2*)(smem + CB_C_LO + off) = make_uint2(pack2(q0, q1), pack2(q2, q3));
        }
        {
            __nv_bfloat16 h0 = __float2bfloat16(vb.x), h1 = __float2bfloat16(vb.y);
            __nv_bfloat16 h2 = __float2bfloat16(vb.z), h3 = __float2bfloat16(vb.w);
            *(uint2*)(smem + CB_B_HI + off) = make_uint2(pack2(h0, h1), pack2(h2, h3));
            __nv_bfloat16 q0 = __float2bfloat16(vb.x - __bfloat162float(h0));
            __nv_bfloat16 q1 = __float2bfloat16(vb.y - __bfloat162float(h1));
            __nv_bfloat16 q2 = __float2bfloat16(vb.z - __bfloat162float(h2));
            __nv_bfloat16 q3 = __float2bfloat16(vb.w - __bfloat162float(h3));
            *(uint2*)(smem + CB_B_LO + off) = make_uint2(pack2(q0, q1), pack2(q2, q3));
        }
    }
    // ---- Xt[p][s] = X[s][p], transposed bf16 hi/lo ----
    for (int u = tid; u < 128 * 8; u += 256) {
        int s = u >> 3, pq = (u & 7) * 4;
        float4 v = *(const float4*)&g_conv[(m0 + s) * CONVD + h * HDIM + pq];
        float vv[4] = {v.x, v.y, v.z, v.w};
        uint32_t kb = (uint32_t)(s >> 6), cs = (uint32_t)((s & 63) * 2);
#pragma unroll
        for (int j = 0; j < 4; j++) {
            __nv_bfloat16 hh = __float2bfloat16(vv[j]);
            __nv_bfloat16 ll = __float2bfloat16(vv[j] - __bfloat162float(hh));
            uint32_t off = SW128((uint32_t)((pq + j) * 128) + cs);
            *(__nv_bfloat16*)(smem + CB_XT_HI + kb * 4096 + off) = hh;
            *(__nv_bfloat16*)(smem + CB_XT_LO + kb * 4096 + off) = ll;
        }
    }
    __syncthreads();

    const int lrow = lane & 15, lcol = lane >> 4;
    const int gr = lane >> 2, gc = (lane & 3) * 2;

    // ---- phase 1: G = C.B^T (3-term split), warp grid 2x4, K=64 ----
    const int wm = (wid >> 2) * 64;
    const int wn = (wid & 3) * 32;
    float acc[4][4][4];
#pragma unroll
    for (int mi = 0; mi < 4; mi++)
#pragma unroll
        for (int ni = 0; ni < 4; ni++)
#pragma unroll
            for (int r = 0; r < 4; r++) acc[mi][ni][r] = 0.f;

    if (!(wm == 0 && wn >= 64)) {
#pragma unroll
        for (int pt = 0; pt < 3; pt++) {
            uint32_t Ab = sb0 + ((pt == 1) ? CB_C_LO : CB_C_HI);
            uint32_t Bb = sb0 + ((pt == 2) ? CB_B_LO : CB_B_HI);
#pragma unroll
            for (int ks = 0; ks < 4; ks++) {
                uint32_t a[4][4], bb[2][4];
#pragma unroll
                for (int mi = 0; mi < 4; mi++)
                    ldsm4(a[mi], Ab + SW128((wm + mi * 16 + lrow) * 128 + (ks * 2 + lcol) * 16));
#pragma unroll
                for (int bi = 0; bi < 2; bi++)
                    ldsm4(bb[bi], Bb + SW128((wn + bi * 16 + lrow) * 128 + (ks * 2 + lcol) * 16));
#pragma unroll
                for (int mi = 0; mi < 4; mi++)
#pragma unroll
                    for (int ni = 0; ni < 4; ni++) {
                        int bi = ni >> 1, hf = ni & 1;
                        mma16816(acc[mi][ni], a[mi], bb[bi][hf], bb[bi][2 + hf]);
                    }
            }
        }
    }
    __syncthreads();

    // ---- epilogue: decay+mask, split M -> smem (overlay C/B) ----
#pragma unroll
    for (int ni = 0; ni < 4; ni++) {
        int s0 = wn + ni * 8;
        float aref = sA[s0];
        int sa = s0 + gc, sb = s0 + gc + 1;
        float es0 = __expf(aref - sA[sa]);
        float es1 = __expf(aref - sA[sb]);
        uint32_t kb = (uint32_t)(s0 >> 6);
        uint32_t cbyte = (uint32_t)(((s0 & 63) + gc) * 2);
#pragma unroll
        for (int mi = 0; mi < 4; mi++) {
#pragma unroll
            for (int half = 0; half < 2; half++) {
                int l = wm + mi * 16 + gr + half * 8;
                float el = __expf(sA[l] - aref);
                float v0 = (l >= sa) ? acc[mi][ni][half * 2 + 0] * el * es0 : 0.f;
                float v1 = (l >= sb) ? acc[mi][ni][half * 2 + 1] * el * es1 : 0.f;
                __nv_bfloat16 h0 = __float2bfloat16(v0), h1 = __float2bfloat16(v1);
                __nv_bfloat16 q0 = __float2bfloat16(v0 - __bfloat162float(h0));
                __nv_bfloat16 q1 = __float2bfloat16(v1 - __bfloat162float(h1));
                uint32_t off = SW128((uint32_t)(l * 128) + cbyte);
                *(uint32_t*)(smem + CB_M_HI + kb * 16384 + off) = pack2(h0, h1);
                *(uint32_t*)(smem + CB_M_LO + kb * 16384 + off) = pack2(q0, q1);
            }
        }
    }
    __syncthreads();

    // ---- phase 2: Y_diag = M @ X ----
    {
        const int l16 = wid * 16;
        float y2[4][4];
#pragma unroll
        for (int ni = 0; ni < 4; ni++)
#pragma unroll
            for (int r = 0; r < 4; r++) y2[ni][r] = 0.f;
#pragma unroll
        for (int pt = 0; pt < 3; pt++) {
            uint32_t Ab = sb0 + ((pt == 1) ? CB_M_LO : CB_M_HI);
            uint32_t Bb = sb0 + ((pt == 2) ? CB_XT_LO : CB_XT_HI);
#pragma unroll
            for (int kb = 0; kb < 2; kb++) {
                uint32_t Abuf = Ab + kb * 16384u;
                uint32_t Bbuf = Bb + kb * 4096u;
#pragma unroll
                for (int ks = 0; ks < 4; ks++) {
                    uint32_t a[4], bb[2][4];
                    ldsm4(a, Abuf + SW128((l16 + lrow) * 128 + (ks * 2 + lcol) * 16));
                    ldsm4(bb[0], Bbuf + SW128((lrow) * 128 + (ks * 2 + lcol) * 16));
                    ldsm4(bb[1], Bbuf + SW128((16 + lrow) * 128 + (ks * 2 + lcol) * 16));
#pragma unroll
                    for (int ni = 0; ni < 4; ni++) {
                        int bi = ni >> 1, hf = ni & 1;
                        mma16816(y2[ni], a, bb[bi][hf], bb[bi][2 + hf]);
                    }
                }
            }
        }
#pragma unroll
        for (int ni = 0; ni < 4; ni++) {
            int p = ni * 8 + gc;
            int l = l16 + gr;
            *(float2*)&g_y[(m0 + l) * DINNER + h * HDIM + p] =
                make_float2(y2[ni][0], y2[ni][1]);
            *(float2*)&g_y[(m0 + l + 8) * DINNER + h * HDIM + p] =
                make_float2(y2[ni][2], y2[ni][3]);
        }
    }
    __syncthreads();   // all M reads done

    // ---- build Btd[n][s] = B[s][n]*ds[s] hi/lo (overlay M area) ----
    for (int u = tid; u < 128 * 16; u += 256) {
        int s = u >> 4, nq = (u & 15) * 4;
        float d = sDs[s];
        float4 v = *(const float4*)&g_conv[(m0 + s) * CONVD + DINNER + h * DST + nq];
        float vv[4] = {v.x * d, v.y * d, v.z * d, v.w * d};
        uint32_t kb = (uint32_t)(s >> 6), cs = (uint32_t)((s & 63) * 2);
#pragma unroll
        for (int j = 0; j < 4; j++) {
            __nv_bfloat16 hh = __float2bfloat16(vv[j]);
            __nv_bfloat16 ll = __float2bfloat16(vv[j] - __bfloat162float(hh));
            uint32_t off = SW128((uint32_t)((nq + j) * 128) + cs);
            *(__nv_bfloat16*)(smem + CB_BTD_HI + kb * 8192 + off) = hh;
            *(__nv_bfloat16*)(smem + CB_BTD_LO + kb * 8192 + off) = ll;
        }
    }
    __syncthreads();

    // ---- phase 3: states = Xt . Btd ----
    {
        const int pm = (wid & 1) * 16;
        const int nn = (wid >> 1) * 16;
        float s3[2][4];
#pragma unroll
        for (int ni = 0; ni < 2; ni++)
#pragma unroll
            for (int r = 0; r < 4; r++) s3[ni][r] = 0.f;
#pragma unroll
        for (int pt = 0; pt < 3; pt++) {
            uint32_t Ab = sb0 + ((pt == 1) ? CB_XT_LO : CB_XT_HI);
            uint32_t Bb = sb0 + ((pt == 2) ? CB_BTD_LO : CB_BTD_HI);
#pragma unroll
            for (int kb = 0; kb < 2; kb++) {
                uint32_t Abuf = Ab + kb * 4096u;
                uint32_t Bbuf = Bb + kb * 8192u;
#pragma unroll
                for (int ks = 0; ks < 4; ks++) {
                    uint32_t a[4], bb[4];
                    ldsm4(a, Abuf + SW128((pm + lrow) * 128 + (ks * 2 + lcol) * 16));
                    ldsm4(bb, Bbuf + SW128((nn + lrow) * 128 + (ks * 2 + lcol) * 16));
                    mma16816(s3[0], a, bb[0], bb[2]);
                    mma16816(s3[1], a, bb[1], bb[3]);
                }
            }
        }
        size_t sbase = ((size_t)((b * NCH + c) * NH + h)) * (HDIM * DST);
#pragma unroll
        for (int ni = 0; ni < 2; ni++) {
            int n = nn + ni * 8 + gc;
            int p0 = pm + gr;
            *(float2*)&g_states[sbase + (size_t)p0 * DST + n] =
                make_float2(s3[ni][0], s3[ni][1]);
            *(float2*)&g_states[sbase + (size_t)(p0 + 8) * DST + n] =
                make_float2(s3[ni][2], s3[ni][3]);
        }
    }
}

// ============================================================
// inter-chunk state scan (per batch)
// ============================================================
__global__ __launch_bounds__(512)
void scan_kernel(int b)
{
    int h = blockIdx.x;
    int tid = threadIdx.x;
    float4 S = make_float4(0.f, 0.f, 0.f, 0.f);
    for (int c = 0; c < NCH; c++) {
        size_t base = ((size_t)((b * NCH + c) * NH + h)) * (HDIM * DST);
        float4 stv = *(const float4*)&g_states[base + tid * 4];
        *(float4*)&g_prevs[base + tid * 4] = S;
        float d = g_dc[(b * NCH + c) * NH + h];
        S.x = S.x * d + stv.x;
        S.y = S.y * d + stv.y;
        S.z = S.z * d + stv.z;
        S.w = S.w * d + stv.w;
    }
}

// ============================================================
// Y_off + D*x skip + SiLU gating -> g_yS [hi|lo]  (per batch)
// ============================================================
__global__ __launch_bounds__(256)
void yoff_kernel(int b, const float* __restrict__ Dvec, const float* __restrict__ z_bias)
{
    extern __shared__ float sm[];
    float* Cs = sm;            // [128][68]
    float* Pv = sm + 128*68;   // [32][68]
    float* eA = sm + 128*68 + 32*68;  // [128]

    const int tid = threadIdx.x;
    const int bid = blockIdx.x;
    const int h = bid & 31;
    const int c = bid >> 5;
    const size_t m0 = (size_t)b * LSEQ + (size_t)c * CHK;
    const size_t pbase = ((size_t)((b * NCH + c) * NH + h)) * (HDIM * DST);

    for (int i = tid; i < CHK * DST; i += 256) {
        int l = i >> 6, n = i & 63;
        Cs[l * 68 + n] = g_conv[(m0 + l) * CONVD + DINNER + NH * DST + h * DST + n];
    }
    for (int i = tid; i < HDIM * DST; i += 256) {
        int p = i >> 6, n = i & 63;
        Pv[p * 68 + n] = g_prevs[pbase + i];
    }
    if (tid < CHK)
        eA[tid] = __expf(g_acum[(m0 + tid) * NH + h]);
    __syncthreads();

    const int p = tid & 31, lg = tid >> 5;
    float4 vp[16];
#pragma unroll
    for (int q = 0; q < 16; q++)
        vp[q] = *(float4*)&Pv[p * 68 + q * 4];
    const float Dh = Dvec[h];
    const int col = h * HDIM + p;
    const float zb = z_bias[col];

#pragma unroll 4
    for (int li = 0; li < 16; li++) {
        int l = lg * 16 + li;
        float acc = 0.f;
#pragma unroll
        for (int q = 0; q < 16; q++) {
            float4 c4 = *(float4*)&Cs[l * 68 + q * 4];
            acc += c4.x * vp[q].x + c4.y * vp[q].y + c4.z * vp[q].z + c4.w * vp[q].w;
        }
        size_t mr = m0 + l;
        float xv = g_conv[mr * CONVD + h * HDIM + p];
        float yv = g_y[mr * DINNER + col] + eA[l] * acc + Dh * xv;
        float zz = g_xbcza[mr * NPROJ + CONVD + col] + zb;
        float sg = 1.f / (1.f + __expf(-zz));
        float gv = yv * (zz * sg);
        __nv_bfloat16 hi = __float2bfloat16(gv);
        __nv_bfloat16 lo = __float2bfloat16(gv - __bfloat162float(hi));
        __nv_bfloat16* yr = g_yS + mr * (size_t)K2;
        yr[col] = hi; yr[1024 + col] = lo;
    }
}

// ============================================================
// launch — asymmetric slice pipeline:
//   G1: [b0 full | b1 front 6144 | b1 last 2048], tail on stream B
// ============================================================
extern "C" void kernel_launch(void* const* d_in, const int* in_sizes, int n_in,
                              void* d_out, int out_size)
{
    (void)in_sizes; (void)n_in; (void)out_size;
    const float* u      = (const float*)d_in[0];
    const float* W_in   = (const float*)d_in[1];
    const float* conv_w = (const float*)d_in[2];
    const float* conv_b = (const float*)d_in[3];
    const float* z_bias = (const float*)d_in[4];
    const float* Dv     = (const float*)d_in[5];
    const float* W_out  = (const float*)d_in[6];
    float* out = (float*)d_out;

    float *p_xbcza = nullptr;
    __nv_bfloat16 *p_uS = nullptr, *p_WinS = nullptr, *p_yS = nullptr, *p_WoutS = nullptr;
    cudaGetSymbolAddress((void**)&p_xbcza, g_xbcza);
    cudaGetSymbolAddress((void**)&p_uS, g_uS);
    cudaGetSymbolAddress((void**)&p_WinS, g_WinS);
    cudaGetSymbolAddress((void**)&p_yS, g_yS);
    cudaGetSymbolAddress((void**)&p_WoutS, g_WoutS);

    static cudaStream_t sB = nullptr;
    static cudaEvent_t ev0 = nullptr, ev1 = nullptr, ev2 = nullptr, evB = nullptr;
    if (!sB) {
        cudaStreamCreateWithFlags(&sB, cudaStreamNonBlocking);
        cudaEventCreateWithFlags(&ev0, cudaEventDisableTiming);
        cudaEventCreateWithFlags(&ev1, cudaEventDisableTiming);
        cudaEventCreateWithFlags(&ev2, cudaEventDisableTiming);
        cudaEventCreateWithFlags(&evB, cudaEventDisableTiming);
    }

    static const size_t GEMM_SMEM = NSTAGE * 32768;  // 96 KB
    static const size_t YOFF_SMEM = (128 * 68 + 32 * 68 + 128) * sizeof(float);
    cudaFuncSetAttribute(gemm_mma, cudaFuncAttributeMaxDynamicSharedMemorySize, (int)GEMM_SMEM);
    cudaFuncSetAttribute(chunk_kernel, cudaFuncAttributeMaxDynamicSharedMemorySize, CB_SMEM);
    cudaFuncSetAttribute(yoff_kernel,  cudaFuncAttributeMaxDynamicSharedMemorySize, (int)YOFF_SMEM);

    const int GN = (NPROJ + BN - 1) / BN;              // 49
    const dim3 g2grid(1024 / BN, LSEQ / BM);           // (8, 64) per batch

    // ---- stream 0: splits ----
    split2<<<MROWS * 2, 256>>>(u, p_uS);
    split2<<<NPROJ * 2, 256>>>(W_in, p_WinS);
    split2<<<1024 * 2, 256>>>(W_out, p_WoutS);

    // ---- G1 piece 0: batch 0 full (8192 rows) ----
    gemm_mma<<<dim3(GN, 64), 256, GEMM_SMEM>>>(p_xbcza, p_uS, p_WinS, NPROJ, NPROJ, 0);
    cudaEventRecord(ev0, 0);
    // ---- G1 piece 1: batch 1 front (6144 rows) ----
    gemm_mma<<<dim3(GN, 48), 256, GEMM_SMEM>>>(p_xbcza, p_uS, p_WinS, NPROJ, NPROJ, LSEQ);
    cudaEventRecord(ev1, 0);
    // ---- G1 piece 2: batch 1 last (2048 rows) ----
    gemm_mma<<<dim3(GN, 16), 256, GEMM_SMEM>>>(p_xbcza, p_uS, p_WinS, NPROJ, NPROJ, LSEQ + 6144);
    cudaEventRecord(ev2, 0);

    // ---- stream B: batch-0 tail (overlaps G1 pieces 1-2) ----
    cudaStreamWaitEvent(sB, ev0, 0);
    conv_kernel<<<dim3(CONVD / 1024, LSEQ / 4), 256, 0, sB>>>(conv_w, conv_b, 0);
    chunk_kernel<<<NCH * NH, 256, CB_SMEM, sB>>>(0, 0);
    scan_kernel<<<NH, 512, 0, sB>>>(0);
    yoff_kernel<<<NCH * NH, 256, YOFF_SMEM, sB>>>(0, Dv, z_bias);
    gemm_mma<<<g2grid, 256, GEMM_SMEM, sB>>>(out, p_yS, p_WoutS, 1024, 1024, 0);

    // ---- stream B: batch-1 front conv+chunk (overlaps G1 piece 2) ----
    cudaStreamWaitEvent(sB, ev1, 0);
    conv_kernel<<<dim3(CONVD / 1024, 6144 / 4), 256, 0, sB>>>(conv_w, conv_b, LSEQ);
    chunk_kernel<<<48 * NH, 256, CB_SMEM, sB>>>(1, 0);

    // ---- stream B: batch-1 last slice + tail ----
    cudaStreamWaitEvent(sB, ev2, 0);
    conv_kernel<<<dim3(CONVD / 1024, 2048 / 4), 256, 0, sB>>>(conv_w, conv_b, LSEQ + 6144);
    chunk_kernel<<<16 * NH, 256, CB_SMEM, sB>>>(1, 48);
    scan_kernel<<<NH, 512, 0, sB>>>(1);
    yoff_kernel<<<NCH * NH, 256, YOFF_SMEM, sB>>>(1, Dv, z_bias);
    gemm_mma<<<g2grid, 256, GEMM_SMEM, sB>>>(out, p_yS, p_WoutS, 1024, 1024, LSEQ);
    cudaEventRecord(evB, sB);

    // ---- join ----
    cudaStreamWaitEvent(0, evB, 0);
}